// round 10
// baseline (speedup 1.0000x reference)
#include <cuda_runtime.h>
#include <cuda_fp16.h>
#include <math.h>
#include <stdint.h>

#define NB    4
#define TSEQ  4096
#define EMB   1024
#define HS    64
#define BTROWS (NB * TSEQ)   // 16384
#define NSPLIT 4
#define NCHUNK 80            // sum over qt=0..31 of floor(qt/8)+1

// Device-global scratch (no allocation)
__device__ __half g_Qh[BTROWS * HS];              // pre-scaled by log2(e)/32
__device__ __half g_Kh[BTROWS * HS];
__device__ __half g_Vh[BTROWS * HS];
__device__ __half g_Wt[192 * EMB];                // [n][k]
__device__ __half g_Oph[NSPLIT * BTROWS * HS];    // partial O per split (fp16)
__device__ float  g_L  [NSPLIT * BTROWS];         // partial l per split

// ---------------------------------------------------------------------------
// helpers
// ---------------------------------------------------------------------------
__device__ __forceinline__ uint32_t smem_u32(const void* p) {
    uint32_t a;
    asm("{ .reg .u64 t; cvta.to.shared.u64 t, %1; cvt.u32.u64 %0, t; }" : "=r"(a) : "l"(p));
    return a;
}
__device__ __forceinline__ void ldsm_x4(uint32_t a, uint32_t* r) {
    asm volatile("ldmatrix.sync.aligned.m8n8.x4.shared.b16 {%0,%1,%2,%3}, [%4];"
                 : "=r"(r[0]), "=r"(r[1]), "=r"(r[2]), "=r"(r[3]) : "r"(a));
}
__device__ __forceinline__ void ldsm_x4t(uint32_t a, uint32_t* r) {
    asm volatile("ldmatrix.sync.aligned.m8n8.x4.trans.shared.b16 {%0,%1,%2,%3}, [%4];"
                 : "=r"(r[0]), "=r"(r[1]), "=r"(r[2]), "=r"(r[3]) : "r"(a));
}
#define MMA16816(C, A0, A1, A2, A3, B0, B1)                                    \
    asm volatile("mma.sync.aligned.m16n8k16.row.col.f32.f16.f16.f32 "          \
                 "{%0,%1,%2,%3}, {%4,%5,%6,%7}, {%8,%9}, {%0,%1,%2,%3};"       \
                 : "+f"((C)[0]), "+f"((C)[1]), "+f"((C)[2]), "+f"((C)[3])      \
                 : "r"(A0), "r"(A1), "r"(A2), "r"(A3), "r"(B0), "r"(B1))
__device__ __forceinline__ uint32_t ex2_h2(uint32_t x) {
    uint32_t r;
    asm("ex2.approx.f16x2 %0, %1;" : "=r"(r) : "r"(x));
    return r;
}
__device__ __forceinline__ void cp16(uint32_t dst, const void* src) {
    asm volatile("cp.async.cg.shared.global [%0], [%1], 16;" :: "r"(dst), "l"(src));
}
#define CP_COMMIT() asm volatile("cp.async.commit_group;" ::: "memory")
#define CP_WAIT0()  asm volatile("cp.async.wait_group 0;" ::: "memory")

// ---------------------------------------------------------------------------
// Kernel 0: coalesced transpose+convert W -> g_Wt[n][k] fp16.
// ---------------------------------------------------------------------------
__global__ void __launch_bounds__(256) wt_kernel(
    const float* __restrict__ Wq, const float* __restrict__ Wk,
    const float* __restrict__ Wv)
{
    __shared__ float ts[32][33];
    const int n0 = (blockIdx.x % 6) * 32;
    const int k0 = (blockIdx.x / 6) * 32;
    const int tx = threadIdx.x & 31;
    const int ty = threadIdx.x >> 5;
    const float* W = (n0 < 64) ? Wq : (n0 < 128) ? Wk : Wv;
    const int nc = n0 & 63;
#pragma unroll
    for (int i = 0; i < 4; ++i) {
        int k = k0 + ty + i * 8;
        ts[ty + i * 8][tx] = W[(size_t)k * 64 + nc + tx];
    }
    __syncthreads();
#pragma unroll
    for (int i = 0; i < 4; ++i) {
        int n = n0 + ty + i * 8;
        g_Wt[(size_t)n * EMB + k0 + tx] = __float2half_rn(ts[tx][ty + i * 8]);
    }
}

// ---------------------------------------------------------------------------
// Kernel 1: QKV GEMM, 128 rows x 192 cols per CTA (grid 128 = one wave).
// (unchanged from R8/R9)
// ---------------------------------------------------------------------------
#define QKV_SMEM 157696
#define XG_OFF   0
#define XS_OFF   65536
#define WS_OFF   102400

__global__ void __launch_bounds__(256) qkv_gemm(const float* __restrict__ x)
{
    extern __shared__ char qsm[];

    const int tid  = threadIdx.x;
    const int lane = tid & 31;
    const int wid  = tid >> 5;
    const int wm   = wid & 3;
    const int wn   = wid >> 2;
    const int g    = lane >> 2;
    const int t    = lane & 3;
    const int t16  = lane & 15;
    const int row0 = blockIdx.x * 128;

    const uint32_t sb = smem_u32(qsm);
    const uint32_t dXG[2] = { sb + XG_OFF, sb + XG_OFF + 32768 };
    const uint32_t dXS[2] = { sb + XS_OFF, sb + XS_OFF + 18432 };
    const uint32_t dWS[2] = { sb + WS_OFF, sb + WS_OFF + 27648 };

    const uint32_t xOff = ((wm * 32 + t16) * 72 + (lane >> 4) * 8) * 2;
    const uint32_t wOff = ((wn * 96 + t16) * 72 + (lane >> 4) * 8) * 2;

    const int xr_r = tid >> 4, xr_c4 = tid & 15;

    float c[2][12][4];
#pragma unroll
    for (int mh = 0; mh < 2; ++mh)
#pragma unroll
        for (int nt = 0; nt < 12; ++nt)
#pragma unroll
            for (int e = 0; e < 4; ++e) c[mh][nt][e] = 0.f;

#pragma unroll
    for (int u = 0; u < 8; ++u) {
        int r = xr_r + 16 * u;
        cp16(dXG[0] + r * 256 + xr_c4 * 16,
             x + (size_t)(row0 + r) * EMB + xr_c4 * 4);
    }
#pragma unroll
    for (int i = tid; i < 1536; i += 256) {
        int r = i >> 3, c8 = i & 7;
        cp16(dWS[0] + (r * 72 + c8 * 8) * 2, g_Wt + (size_t)r * EMB + c8 * 8);
    }
    CP_COMMIT();

    int buf = 0;
    for (int it = 0; it < 16; ++it, buf ^= 1) {
        const int cc = it * 64;
        CP_WAIT0();
        __syncthreads();

#pragma unroll
        for (int u = 0; u < 8; ++u) {
            int r = xr_r + 16 * u;
            float4 f = *(const float4*)(qsm + XG_OFF + (buf ? 32768 : 0)
                                            + r * 256 + xr_c4 * 16);
            __half2 h01 = __floats2half2_rn(f.x, f.y);
            __half2 h23 = __floats2half2_rn(f.z, f.w);
            uint2 uh;
            uh.x = *(uint32_t*)&h01; uh.y = *(uint32_t*)&h23;
            *(uint2*)(qsm + XS_OFF + (buf ? 18432 : 0) + r * 144 + xr_c4 * 8) = uh;
        }
        __syncthreads();

        if (it + 1 < 16) {
#pragma unroll
            for (int u = 0; u < 8; ++u) {
                int r = xr_r + 16 * u;
                cp16(dXG[buf ^ 1] + r * 256 + xr_c4 * 16,
                     x + (size_t)(row0 + r) * EMB + cc + 64 + xr_c4 * 4);
            }
#pragma unroll
            for (int i = tid; i < 1536; i += 256) {
                int r = i >> 3, c8 = i & 7;
                cp16(dWS[buf ^ 1] + (r * 72 + c8 * 8) * 2,
                     g_Wt + (size_t)r * EMB + cc + 64 + c8 * 8);
            }
            CP_COMMIT();
        }

        const uint32_t aX = dXS[buf] + xOff;
        const uint32_t aW = dWS[buf] + wOff;
#pragma unroll
        for (int ks = 0; ks < 4; ++ks) {
            uint32_t ah[2][4];
            ldsm_x4(aX + ks * 32, ah[0]);
            ldsm_x4(aX + 16 * 144 + ks * 32, ah[1]);
#pragma unroll
            for (int np = 0; np < 6; ++np) {
                uint32_t bw[4];
                ldsm_x4(aW + (np * 16 * 72 + ks * 16) * 2, bw);
#pragma unroll
                for (int mh = 0; mh < 2; ++mh) {
                    MMA16816(c[mh][2 * np + 0], ah[mh][0], ah[mh][1], ah[mh][2], ah[mh][3],
                             bw[0], bw[2]);
                    MMA16816(c[mh][2 * np + 1], ah[mh][0], ah[mh][1], ah[mh][2], ah[mh][3],
                             bw[1], bw[3]);
                }
            }
        }
    }

#pragma unroll
    for (int mh = 0; mh < 2; ++mh) {
        const int r0 = row0 + wm * 32 + mh * 16 + g;
#pragma unroll
        for (int nt = 0; nt < 12; ++nt) {
            int n0 = wn * 96 + nt * 8 + 2 * t;
            int mat = n0 >> 6, col = n0 & 63;
            __half* base = (mat == 0) ? g_Qh : (mat == 1) ? g_Kh : g_Vh;
            float sc = (mat == 0) ? 0.045084220f : 1.0f;
            __half2 v0 = __floats2half2_rn(c[mh][nt][0] * sc, c[mh][nt][1] * sc);
            __half2 v1 = __floats2half2_rn(c[mh][nt][2] * sc, c[mh][nt][3] * sc);
            *(__half2*)(base + (size_t)r0 * HS + col)       = v0;
            *(__half2*)(base + (size_t)(r0 + 8) * HS + col) = v1;
        }
    }
}

// ---------------------------------------------------------------------------
// Kernel 2: causal attention. 128-query CTAs (8 warps); warp = 16 rows x all
// 64 keys; register-resident P; cp.async double-buffered K/V.
// Chunks of <=16 key-tiles: splits(qt) = floor(qt/8)+1 over 32 q-tiles.
// Dynamic smem: Q 18432 + K[2] 2*9216 + V[2] 2*9216 = 55296 bytes.
// ---------------------------------------------------------------------------
#define ATT_SMEM 55296

__global__ void __launch_bounds__(256, 2) attn_kernel()
{
    extern __shared__ char asm_[];
    __half* Qs = (__half*)asm_;                       // [128][72]
    const uint32_t sb = smem_u32(asm_);
    const uint32_t dK[2] = { sb + 18432, sb + 27648 };
    const uint32_t dV[2] = { sb + 36864, sb + 46080 };

    const int tid  = threadIdx.x;
    const int lane = tid & 31;
    const int wm   = tid >> 5;       // 0..7
    const int g    = lane >> 2;
    const int t    = lane & 3;
    const int t16  = lane & 15;
    const int b    = blockIdx.y;

    // ---- chunk -> (qt, ci, [k0,k1)); group gg = floor(qt/8), gg+1 chunks/qt
    int cid = (NCHUNK - 1) - (int)blockIdx.x;   // heavy chunks first
    int gg = 3;
    while (cid < 4 * gg * (gg + 1)) --gg;
    int off = cid - 4 * gg * (gg + 1);
    int qt  = 8 * gg + off / (gg + 1);
    int ci  = off % (gg + 1);
    int nt_ = 2 * qt + 2;
    int k0 = ci * nt_ / (gg + 1);
    int k1 = (ci + 1) * nt_ / (gg + 1);
    const int qbase = qt * 128;

    const __half* Kg = g_Kh + (size_t)b * TSEQ * HS;
    const __half* Vg = g_Vh + (size_t)b * TSEQ * HS;

    // ---- stage Q [128 x 64]
    {
        const uint4* Qgp = (const uint4*)(g_Qh + ((size_t)b * TSEQ + qbase) * HS);
#pragma unroll
        for (int i = tid; i < 1024; i += 256) {
            int r = i >> 3, c8 = i & 7;
            *(uint4*)(Qs + r * 72 + c8 * 8) = Qgp[i];
        }
    }
    // ---- cp.async first K/V tile into buf 0
    {
        const __half* ks = Kg + (size_t)k0 * 64 * HS;
        const __half* vs = Vg + (size_t)k0 * 64 * HS;
#pragma unroll
        for (int i = tid; i < 512; i += 256) {
            int r = i >> 3, c8 = i & 7;
            cp16(dK[0] + (r * 72 + c8 * 8) * 2, ks + i * 8);
            cp16(dV[0] + (r * 72 + c8 * 8) * 2, vs + i * 8);
        }
        CP_COMMIT();
    }
    CP_WAIT0();
    __syncthreads();

    // ---- Q fragments (tile-invariant, registers)
    uint32_t qf[4][4];
    {
        const uint32_t aQ = sb + ((wm * 16 + t16) * 72 + (lane >> 4) * 8) * 2;
#pragma unroll
        for (int ks = 0; ks < 4; ++ks) ldsm_x4(aQ + ks * 32, qf[ks]);
    }

    const uint32_t offK = (((lane & 7) + ((lane & 16) >> 1)) * 72 + ((lane >> 3) & 1) * 8) * 2;
    const uint32_t offV = ((lane & 15) * 72 + ((lane & 16) >> 1)) * 2;

    float o[8][4];
#pragma unroll
    for (int nt = 0; nt < 8; ++nt)
#pragma unroll
        for (int e = 0; e < 4; ++e) o[nt][e] = 0.f;
    float lsum0 = 0.f, lsum1 = 0.f;

    const int row0 = qbase + wm * 16 + g;

    int buf = 0;
    for (int kt = k0; kt < k1; ++kt, buf ^= 1) {
        if (kt + 1 < k1) {
            const __half* ks = Kg + (size_t)(kt + 1) * 64 * HS;
            const __half* vs = Vg + (size_t)(kt + 1) * 64 * HS;
#pragma unroll
            for (int i = tid; i < 512; i += 256) {
                int r = i >> 3, c8 = i & 7;
                cp16(dK[buf ^ 1] + (r * 72 + c8 * 8) * 2, ks + i * 8);
                cp16(dV[buf ^ 1] + (r * 72 + c8 * 8) * 2, vs + i * 8);
            }
            CP_COMMIT();
        }

        // ---- S = Q . K^T  (Q carries log2(e)/sqrt(C))
        float c[8][4];
#pragma unroll
        for (int nt = 0; nt < 8; ++nt)
#pragma unroll
            for (int e = 0; e < 4; ++e) c[nt][e] = 0.f;
        const uint32_t sKb = dK[buf] + offK;
#pragma unroll
        for (int ks = 0; ks < 4; ++ks) {
            uint32_t kr[4][4];
#pragma unroll
            for (int np = 0; np < 4; ++np)
                ldsm_x4(sKb + (np * 16 * 72 + ks * 16) * 2, kr[np]);
#pragma unroll
            for (int nt = 0; nt < 8; ++nt)
                MMA16816(c[nt], qf[ks][0], qf[ks][1], qf[ks][2], qf[ks][3],
                         kr[nt >> 1][(nt & 1) * 2], kr[nt >> 1][(nt & 1) * 2 + 1]);
        }

        // ---- softmax (fixed max), fp16x2 exp -> P fragments
        const bool diag = (kt >= 2 * qt);
        uint32_t pk[8][2];
        __half2 lacc0 = __float2half2_rn(0.f), lacc1 = __float2half2_rn(0.f);
#pragma unroll
        for (int nt = 0; nt < 8; ++nt) {
            const int col0 = kt * 64 + nt * 8 + 2 * t;
            float s0 = c[nt][0];
            float s1 = c[nt][1];
            float s2 = c[nt][2];
            float s3 = c[nt][3];
            if (diag) {
                if (col0     > row0)     s0 = -1e30f;
                if (col0 + 1 > row0)     s1 = -1e30f;
                if (col0     > row0 + 8) s2 = -1e30f;
                if (col0 + 1 > row0 + 8) s3 = -1e30f;
            }
            __half2 h01 = __floats2half2_rn(s0, s1);
            __half2 h23 = __floats2half2_rn(s2, s3);
            uint32_t p01 = ex2_h2(*(uint32_t*)&h01);
            uint32_t p23 = ex2_h2(*(uint32_t*)&h23);
            pk[nt][0] = p01;
            pk[nt][1] = p23;
            lacc0 = __hadd2(lacc0, *(__half2*)&p01);
            lacc1 = __hadd2(lacc1, *(__half2*)&p23);
        }
        lsum0 += __low2float(lacc0) + __high2float(lacc0);
        lsum1 += __low2float(lacc1) + __high2float(lacc1);

        // ---- O += P . V
        const uint32_t sVb = dV[buf] + offV;
#pragma unroll
        for (int ks = 0; ks < 4; ++ks) {
            uint32_t vr[4][4];
#pragma unroll
            for (int np = 0; np < 4; ++np)
                ldsm_x4t(sVb + (ks * 16 * 72 + np * 16) * 2, vr[np]);
#pragma unroll
            for (int nt = 0; nt < 8; ++nt)
                MMA16816(o[nt], pk[2 * ks][0], pk[2 * ks][1],
                         pk[2 * ks + 1][0], pk[2 * ks + 1][1],
                         vr[nt >> 1][(nt & 1) * 2], vr[nt >> 1][(nt & 1) * 2 + 1]);
        }

        if (kt + 1 < k1) {
            CP_WAIT0();
            __syncthreads();
        }
    }

    // ---- epilogue
    lsum0 += __shfl_xor_sync(0xffffffffu, lsum0, 1);
    lsum0 += __shfl_xor_sync(0xffffffffu, lsum0, 2);
    lsum1 += __shfl_xor_sync(0xffffffffu, lsum1, 1);
    lsum1 += __shfl_xor_sync(0xffffffffu, lsum1, 2);

    const size_t pbase = (size_t)(ci * NB + b) * TSEQ + qbase + wm * 16 + g;
    if (t == 0) {
        g_L[pbase]     = lsum0;
        g_L[pbase + 8] = lsum1;
    }

    __half* og0 = g_Oph + pbase * HS + 2 * t;
    __half* og1 = og0 + 8 * HS;
#pragma unroll
    for (int nt = 0; nt < 8; ++nt) {
        *(__half2*)(og0 + nt * 8) = __floats2half2_rn(o[nt][0], o[nt][1]);
        *(__half2*)(og1 + nt * 8) = __floats2half2_rn(o[nt][2], o[nt][3]);
    }
}

// ---------------------------------------------------------------------------
// Kernel 3: combine <=4 splits, fully unrolled with predication (MLP=4).
// splits(row) = (tt>>10)+1, tt = row % TSEQ.
// ---------------------------------------------------------------------------
__global__ void __launch_bounds__(256) combine_kernel(float* __restrict__ Out)
{
    int idx = blockIdx.x * 256 + threadIdx.x;   // over BTROWS*16
    int r = idx >> 4;
    int tt = r & (TSEQ - 1);
    int ns = (tt >> 10) + 1;                    // floor(qt/8)+1, qt = tt>>7

    const __half* base = g_Oph + (size_t)idx * 4;
    float la = 0.f, lb = 0.f;
    float a0 = 0.f, a1 = 0.f, a2 = 0.f, a3 = 0.f;
    float b0 = 0.f, b1 = 0.f, b2 = 0.f, b3 = 0.f;

    // s = 0 always present
    {
        la += g_L[r];
        uint2 u = *(const uint2*)base;
        float2 f0 = __half22float2(*(__half2*)&u.x);
        float2 f1 = __half22float2(*(__half2*)&u.y);
        a0 += f0.x; a1 += f0.y; a2 += f1.x; a3 += f1.y;
    }
    if (1 < ns) {
        lb += g_L[(size_t)BTROWS + r];
        uint2 u = *(const uint2*)(base + (size_t)BTROWS * HS);
        float2 f0 = __half22float2(*(__half2*)&u.x);
        float2 f1 = __half22float2(*(__half2*)&u.y);
        b0 += f0.x; b1 += f0.y; b2 += f1.x; b3 += f1.y;
    }
    if (2 < ns) {
        la += g_L[(size_t)2 * BTROWS + r];
        uint2 u = *(const uint2*)(base + (size_t)2 * BTROWS * HS);
        float2 f0 = __half22float2(*(__half2*)&u.x);
        float2 f1 = __half22float2(*(__half2*)&u.y);
        a0 += f0.x; a1 += f0.y; a2 += f1.x; a3 += f1.y;
    }
    if (3 < ns) {
        lb += g_L[(size_t)3 * BTROWS + r];
        uint2 u = *(const uint2*)(base + (size_t)3 * BTROWS * HS);
        float2 f0 = __half22float2(*(__half2*)&u.x);
        float2 f1 = __half22float2(*(__half2*)&u.y);
        b0 += f0.x; b1 += f0.y; b2 += f1.x; b3 += f1.y;
    }

    float rinv = 1.f / (la + lb);
    float4 v;
    v.x = (a0 + b0) * rinv;
    v.y = (a1 + b1) * rinv;
    v.z = (a2 + b2) * rinv;
    v.w = (a3 + b3) * rinv;
    ((float4*)Out)[idx] = v;
}

// ---------------------------------------------------------------------------
extern "C" void kernel_launch(void* const* d_in, const int* in_sizes, int n_in,
                              void* d_out, int out_size)
{
    const float* x  = (const float*)d_in[0];
    const float* Wq = (const float*)d_in[1];
    const float* Wk = (const float*)d_in[2];
    const float* Wv = (const float*)d_in[3];
    float* Out = (float*)d_out;

    static int configured = 0;
    if (!configured) {
        cudaFuncSetAttribute(qkv_gemm,
                             cudaFuncAttributeMaxDynamicSharedMemorySize, QKV_SMEM);
        cudaFuncSetAttribute(attn_kernel,
                             cudaFuncAttributeMaxDynamicSharedMemorySize, ATT_SMEM);
        configured = 1;
    }

    wt_kernel<<<192, 256>>>(Wq, Wk, Wv);
    qkv_gemm<<<BTROWS / 128, 256, QKV_SMEM>>>(x);
    attn_kernel<<<dim3(NCHUNK, NB), 256, ATT_SMEM>>>();
    combine_kernel<<<BTROWS * 16 / 256, 256>>>(Out);
}

// round 11
// speedup vs baseline: 1.0898x; 1.0898x over previous
#include <cuda_runtime.h>
#include <cuda_fp16.h>
#include <math.h>
#include <stdint.h>

#define NB    4
#define TSEQ  4096
#define EMB   1024
#define HS    64
#define BTROWS (NB * TSEQ)   // 16384
#define NSPLIT 8
#define NCHUNK 144           // sum over qt=0..31 of floor(qt/4)+1

// Device-global scratch (no allocation)
__device__ __half g_Qh[BTROWS * HS];              // pre-scaled by log2(e)/32
__device__ __half g_Kh[BTROWS * HS];
__device__ __half g_Vh[BTROWS * HS];
__device__ __half g_Wt[192 * EMB];                // [n][k]
__device__ __half g_Oph[NSPLIT * BTROWS * HS];    // partial O per split (fp16)
__device__ float  g_L  [NSPLIT * BTROWS];         // partial l per split

// ---------------------------------------------------------------------------
// helpers
// ---------------------------------------------------------------------------
__device__ __forceinline__ uint32_t smem_u32(const void* p) {
    uint32_t a;
    asm("{ .reg .u64 t; cvta.to.shared.u64 t, %1; cvt.u32.u64 %0, t; }" : "=r"(a) : "l"(p));
    return a;
}
__device__ __forceinline__ void ldsm_x4(uint32_t a, uint32_t* r) {
    asm volatile("ldmatrix.sync.aligned.m8n8.x4.shared.b16 {%0,%1,%2,%3}, [%4];"
                 : "=r"(r[0]), "=r"(r[1]), "=r"(r[2]), "=r"(r[3]) : "r"(a));
}
__device__ __forceinline__ void ldsm_x4t(uint32_t a, uint32_t* r) {
    asm volatile("ldmatrix.sync.aligned.m8n8.x4.trans.shared.b16 {%0,%1,%2,%3}, [%4];"
                 : "=r"(r[0]), "=r"(r[1]), "=r"(r[2]), "=r"(r[3]) : "r"(a));
}
// fp32-accumulate (PV, QKV)
#define MMA16816(C, A0, A1, A2, A3, B0, B1)                                    \
    asm volatile("mma.sync.aligned.m16n8k16.row.col.f32.f16.f16.f32 "          \
                 "{%0,%1,%2,%3}, {%4,%5,%6,%7}, {%8,%9}, {%0,%1,%2,%3};"       \
                 : "+f"((C)[0]), "+f"((C)[1]), "+f"((C)[2]), "+f"((C)[3])      \
                 : "r"(A0), "r"(A1), "r"(A2), "r"(A3), "r"(B0), "r"(B1))
// fp16-accumulate (S only): D = {row g | row g+8} packed half2
#define MMA16816H(C0, C1, A0, A1, A2, A3, B0, B1)                              \
    asm volatile("mma.sync.aligned.m16n8k16.row.col.f16.f16.f16.f16 "          \
                 "{%0,%1}, {%2,%3,%4,%5}, {%6,%7}, {%0,%1};"                   \
                 : "+r"(C0), "+r"(C1)                                          \
                 : "r"(A0), "r"(A1), "r"(A2), "r"(A3), "r"(B0), "r"(B1))
__device__ __forceinline__ uint32_t ex2_h2(uint32_t x) {
    uint32_t r;
    asm("ex2.approx.f16x2 %0, %1;" : "=r"(r) : "r"(x));
    return r;
}
__device__ __forceinline__ void cp16(uint32_t dst, const void* src) {
    asm volatile("cp.async.cg.shared.global [%0], [%1], 16;" :: "r"(dst), "l"(src));
}
#define CP_COMMIT() asm volatile("cp.async.commit_group;" ::: "memory")
#define CP_WAIT0()  asm volatile("cp.async.wait_group 0;" ::: "memory")

// half -60.0: ex2(-60) underflows to exactly 0 in fp16
#define HNEG60 0xD380u

// ---------------------------------------------------------------------------
// Kernel 0: coalesced transpose+convert W -> g_Wt[n][k] fp16.
// ---------------------------------------------------------------------------
__global__ void __launch_bounds__(256) wt_kernel(
    const float* __restrict__ Wq, const float* __restrict__ Wk,
    const float* __restrict__ Wv)
{
    __shared__ float ts[32][33];
    const int n0 = (blockIdx.x % 6) * 32;
    const int k0 = (blockIdx.x / 6) * 32;
    const int tx = threadIdx.x & 31;
    const int ty = threadIdx.x >> 5;
    const float* W = (n0 < 64) ? Wq : (n0 < 128) ? Wk : Wv;
    const int nc = n0 & 63;
#pragma unroll
    for (int i = 0; i < 4; ++i) {
        int k = k0 + ty + i * 8;
        ts[ty + i * 8][tx] = W[(size_t)k * 64 + nc + tx];
    }
    __syncthreads();
#pragma unroll
    for (int i = 0; i < 4; ++i) {
        int n = n0 + ty + i * 8;
        g_Wt[(size_t)n * EMB + k0 + tx] = __float2half_rn(ts[tx][ty + i * 8]);
    }
}

// ---------------------------------------------------------------------------
// Kernel 1: QKV GEMM, 128 rows x 192 cols per CTA (grid 128 = one wave).
// ---------------------------------------------------------------------------
#define QKV_SMEM 157696
#define XG_OFF   0
#define XS_OFF   65536
#define WS_OFF   102400

__global__ void __launch_bounds__(256) qkv_gemm(const float* __restrict__ x)
{
    extern __shared__ char qsm[];

    const int tid  = threadIdx.x;
    const int lane = tid & 31;
    const int wid  = tid >> 5;
    const int wm   = wid & 3;
    const int wn   = wid >> 2;
    const int g    = lane >> 2;
    const int t    = lane & 3;
    const int t16  = lane & 15;
    const int row0 = blockIdx.x * 128;

    const uint32_t sb = smem_u32(qsm);
    const uint32_t dXG[2] = { sb + XG_OFF, sb + XG_OFF + 32768 };
    const uint32_t dXS[2] = { sb + XS_OFF, sb + XS_OFF + 18432 };
    const uint32_t dWS[2] = { sb + WS_OFF, sb + WS_OFF + 27648 };

    const uint32_t xOff = ((wm * 32 + t16) * 72 + (lane >> 4) * 8) * 2;
    const uint32_t wOff = ((wn * 96 + t16) * 72 + (lane >> 4) * 8) * 2;

    const int xr_r = tid >> 4, xr_c4 = tid & 15;

    float c[2][12][4];
#pragma unroll
    for (int mh = 0; mh < 2; ++mh)
#pragma unroll
        for (int nt = 0; nt < 12; ++nt)
#pragma unroll
            for (int e = 0; e < 4; ++e) c[mh][nt][e] = 0.f;

#pragma unroll
    for (int u = 0; u < 8; ++u) {
        int r = xr_r + 16 * u;
        cp16(dXG[0] + r * 256 + xr_c4 * 16,
             x + (size_t)(row0 + r) * EMB + xr_c4 * 4);
    }
#pragma unroll
    for (int i = tid; i < 1536; i += 256) {
        int r = i >> 3, c8 = i & 7;
        cp16(dWS[0] + (r * 72 + c8 * 8) * 2, g_Wt + (size_t)r * EMB + c8 * 8);
    }
    CP_COMMIT();

    int buf = 0;
    for (int it = 0; it < 16; ++it, buf ^= 1) {
        const int cc = it * 64;
        CP_WAIT0();
        __syncthreads();

#pragma unroll
        for (int u = 0; u < 8; ++u) {
            int r = xr_r + 16 * u;
            float4 f = *(const float4*)(qsm + XG_OFF + (buf ? 32768 : 0)
                                            + r * 256 + xr_c4 * 16);
            __half2 h01 = __floats2half2_rn(f.x, f.y);
            __half2 h23 = __floats2half2_rn(f.z, f.w);
            uint2 uh;
            uh.x = *(uint32_t*)&h01; uh.y = *(uint32_t*)&h23;
            *(uint2*)(qsm + XS_OFF + (buf ? 18432 : 0) + r * 144 + xr_c4 * 8) = uh;
        }
        __syncthreads();

        if (it + 1 < 16) {
#pragma unroll
            for (int u = 0; u < 8; ++u) {
                int r = xr_r + 16 * u;
                cp16(dXG[buf ^ 1] + r * 256 + xr_c4 * 16,
                     x + (size_t)(row0 + r) * EMB + cc + 64 + xr_c4 * 4);
            }
#pragma unroll
            for (int i = tid; i < 1536; i += 256) {
                int r = i >> 3, c8 = i & 7;
                cp16(dWS[buf ^ 1] + (r * 72 + c8 * 8) * 2,
                     g_Wt + (size_t)r * EMB + cc + 64 + c8 * 8);
            }
            CP_COMMIT();
        }

        const uint32_t aX = dXS[buf] + xOff;
        const uint32_t aW = dWS[buf] + wOff;
#pragma unroll
        for (int ks = 0; ks < 4; ++ks) {
            uint32_t ah[2][4];
            ldsm_x4(aX + ks * 32, ah[0]);
            ldsm_x4(aX + 16 * 144 + ks * 32, ah[1]);
#pragma unroll
            for (int np = 0; np < 6; ++np) {
                uint32_t bw[4];
                ldsm_x4(aW + (np * 16 * 72 + ks * 16) * 2, bw);
#pragma unroll
                for (int mh = 0; mh < 2; ++mh) {
                    MMA16816(c[mh][2 * np + 0], ah[mh][0], ah[mh][1], ah[mh][2], ah[mh][3],
                             bw[0], bw[2]);
                    MMA16816(c[mh][2 * np + 1], ah[mh][0], ah[mh][1], ah[mh][2], ah[mh][3],
                             bw[1], bw[3]);
                }
            }
        }
    }

#pragma unroll
    for (int mh = 0; mh < 2; ++mh) {
        const int r0 = row0 + wm * 32 + mh * 16 + g;
#pragma unroll
        for (int nt = 0; nt < 12; ++nt) {
            int n0 = wn * 96 + nt * 8 + 2 * t;
            int mat = n0 >> 6, col = n0 & 63;
            __half* base = (mat == 0) ? g_Qh : (mat == 1) ? g_Kh : g_Vh;
            float sc = (mat == 0) ? 0.045084220f : 1.0f;
            __half2 v0 = __floats2half2_rn(c[mh][nt][0] * sc, c[mh][nt][1] * sc);
            __half2 v1 = __floats2half2_rn(c[mh][nt][2] * sc, c[mh][nt][3] * sc);
            *(__half2*)(base + (size_t)r0 * HS + col)       = v0;
            *(__half2*)(base + (size_t)(r0 + 8) * HS + col) = v1;
        }
    }
}

// ---------------------------------------------------------------------------
// Kernel 2: causal attention (R9 schedule: chunks of <=8 key-tiles).
// 128-query CTAs, 8 warps; warp = 16 rows x all 64 keys; register-resident P.
// S computed with fp16 accumulators (2x HMMA rate, no cvt in softmax);
// PV stays fp32-acc. Masking splices -60.0h into the packed accumulator.
// ---------------------------------------------------------------------------
#define ATT_SMEM 55296

__global__ void __launch_bounds__(256, 2) attn_kernel()
{
    extern __shared__ char asm_[];
    __half* Qs = (__half*)asm_;                       // [128][72]
    const uint32_t sb = smem_u32(asm_);
    const uint32_t dK[2] = { sb + 18432, sb + 27648 };
    const uint32_t dV[2] = { sb + 36864, sb + 46080 };

    const int tid  = threadIdx.x;
    const int lane = tid & 31;
    const int wm   = tid >> 5;       // 0..7
    const int g    = lane >> 2;
    const int t    = lane & 3;
    const int t16  = lane & 15;
    const int b    = blockIdx.y;

    // ---- chunk -> (qt, ci, [k0,k1)); splits(qt) = floor(qt/4)+1
    int cid = (NCHUNK - 1) - (int)blockIdx.x;   // heavy chunks first
    int gg = 7;
    while (cid < 2 * gg * (gg + 1)) --gg;
    int off = cid - 2 * gg * (gg + 1);
    int qt  = 4 * gg + off / (gg + 1);
    int ci  = off % (gg + 1);
    int nt_ = 2 * qt + 2;
    int k0 = ci * nt_ / (gg + 1);
    int k1 = (ci + 1) * nt_ / (gg + 1);
    const int qbase = qt * 128;

    const __half* Kg = g_Kh + (size_t)b * TSEQ * HS;
    const __half* Vg = g_Vh + (size_t)b * TSEQ * HS;

    // ---- stage Q [128 x 64]
    {
        const uint4* Qgp = (const uint4*)(g_Qh + ((size_t)b * TSEQ + qbase) * HS);
#pragma unroll
        for (int i = tid; i < 1024; i += 256) {
            int r = i >> 3, c8 = i & 7;
            *(uint4*)(Qs + r * 72 + c8 * 8) = Qgp[i];
        }
    }
    // ---- cp.async first K/V tile into buf 0
    {
        const __half* ks = Kg + (size_t)k0 * 64 * HS;
        const __half* vs = Vg + (size_t)k0 * 64 * HS;
#pragma unroll
        for (int i = tid; i < 512; i += 256) {
            int r = i >> 3, c8 = i & 7;
            cp16(dK[0] + (r * 72 + c8 * 8) * 2, ks + i * 8);
            cp16(dV[0] + (r * 72 + c8 * 8) * 2, vs + i * 8);
        }
        CP_COMMIT();
    }
    CP_WAIT0();
    __syncthreads();

    // ---- Q fragments (tile-invariant, registers)
    uint32_t qf[4][4];
    {
        const uint32_t aQ = sb + ((wm * 16 + t16) * 72 + (lane >> 4) * 8) * 2;
#pragma unroll
        for (int ks = 0; ks < 4; ++ks) ldsm_x4(aQ + ks * 32, qf[ks]);
    }

    const uint32_t offK = (((lane & 7) + ((lane & 16) >> 1)) * 72 + ((lane >> 3) & 1) * 8) * 2;
    const uint32_t offV = ((lane & 15) * 72 + ((lane & 16) >> 1)) * 2;

    float o[8][4];
#pragma unroll
    for (int nt = 0; nt < 8; ++nt)
#pragma unroll
        for (int e = 0; e < 4; ++e) o[nt][e] = 0.f;
    float lsum0 = 0.f, lsum1 = 0.f;

    const int row0 = qbase + wm * 16 + g;

    int buf = 0;
    for (int kt = k0; kt < k1; ++kt, buf ^= 1) {
        if (kt + 1 < k1) {
            const __half* ks = Kg + (size_t)(kt + 1) * 64 * HS;
            const __half* vs = Vg + (size_t)(kt + 1) * 64 * HS;
#pragma unroll
            for (int i = tid; i < 512; i += 256) {
                int r = i >> 3, c8 = i & 7;
                cp16(dK[buf ^ 1] + (r * 72 + c8 * 8) * 2, ks + i * 8);
                cp16(dV[buf ^ 1] + (r * 72 + c8 * 8) * 2, vs + i * 8);
            }
            CP_COMMIT();
        }

        // ---- S = Q . K^T  (fp16 accumulate; Q carries log2(e)/sqrt(C))
        uint32_t ch[8][2];
#pragma unroll
        for (int nt = 0; nt < 8; ++nt) { ch[nt][0] = 0u; ch[nt][1] = 0u; }
        const uint32_t sKb = dK[buf] + offK;
#pragma unroll
        for (int ks = 0; ks < 4; ++ks) {
            uint32_t kr[4][4];
#pragma unroll
            for (int np = 0; np < 4; ++np)
                ldsm_x4(sKb + (np * 16 * 72 + ks * 16) * 2, kr[np]);
#pragma unroll
            for (int nt = 0; nt < 8; ++nt)
                MMA16816H(ch[nt][0], ch[nt][1],
                          qf[ks][0], qf[ks][1], qf[ks][2], qf[ks][3],
                          kr[nt >> 1][(nt & 1) * 2], kr[nt >> 1][(nt & 1) * 2 + 1]);
        }

        // ---- softmax (fixed max): mask by byte-splice, ex2 directly
        const bool diag = (kt >= 2 * qt);
        uint32_t pk[8][2];
        __half2 lacc0 = __float2half2_rn(0.f), lacc1 = __float2half2_rn(0.f);
#pragma unroll
        for (int nt = 0; nt < 8; ++nt) {
            uint32_t v0 = ch[nt][0];   // row g,   cols 2t, 2t+1 (packed)
            uint32_t v1 = ch[nt][1];   // row g+8, cols 2t, 2t+1
            if (diag) {
                const int col0 = kt * 64 + nt * 8 + 2 * t;
                if (col0     > row0)     v0 = (v0 & 0xFFFF0000u) | HNEG60;
                if (col0 + 1 > row0)     v0 = (v0 & 0x0000FFFFu) | (HNEG60 << 16);
                if (col0     > row0 + 8) v1 = (v1 & 0xFFFF0000u) | HNEG60;
                if (col0 + 1 > row0 + 8) v1 = (v1 & 0x0000FFFFu) | (HNEG60 << 16);
            }
            uint32_t p01 = ex2_h2(v0);
            uint32_t p23 = ex2_h2(v1);
            pk[nt][0] = p01;
            pk[nt][1] = p23;
            lacc0 = __hadd2(lacc0, *(__half2*)&p01);
            lacc1 = __hadd2(lacc1, *(__half2*)&p23);
        }
        lsum0 += __low2float(lacc0) + __high2float(lacc0);
        lsum1 += __low2float(lacc1) + __high2float(lacc1);

        // ---- O += P . V  (fp32 accumulate)
        const uint32_t sVb = dV[buf] + offV;
#pragma unroll
        for (int ks = 0; ks < 4; ++ks) {
            uint32_t vr[4][4];
#pragma unroll
            for (int np = 0; np < 4; ++np)
                ldsm_x4t(sVb + (ks * 16 * 72 + np * 16) * 2, vr[np]);
#pragma unroll
            for (int nt = 0; nt < 8; ++nt)
                MMA16816(o[nt], pk[2 * ks][0], pk[2 * ks][1],
                         pk[2 * ks + 1][0], pk[2 * ks + 1][1],
                         vr[nt >> 1][(nt & 1) * 2], vr[nt >> 1][(nt & 1) * 2 + 1]);
        }

        if (kt + 1 < k1) {
            CP_WAIT0();
            __syncthreads();
        }
    }

    // ---- epilogue
    lsum0 += __shfl_xor_sync(0xffffffffu, lsum0, 1);
    lsum0 += __shfl_xor_sync(0xffffffffu, lsum0, 2);
    lsum1 += __shfl_xor_sync(0xffffffffu, lsum1, 1);
    lsum1 += __shfl_xor_sync(0xffffffffu, lsum1, 2);

    const size_t pbase = (size_t)(ci * NB + b) * TSEQ + qbase + wm * 16 + g;
    if (t == 0) {
        g_L[pbase]     = lsum0;
        g_L[pbase + 8] = lsum1;
    }

    __half* og0 = g_Oph + pbase * HS + 2 * t;
    __half* og1 = og0 + 8 * HS;
#pragma unroll
    for (int nt = 0; nt < 8; ++nt) {
        *(__half2*)(og0 + nt * 8) = __floats2half2_rn(o[nt][0], o[nt][1]);
        *(__half2*)(og1 + nt * 8) = __floats2half2_rn(o[nt][2], o[nt][3]);
    }
}

// ---------------------------------------------------------------------------
// Kernel 3: combine <=8 splits, fully unrolled with predication (MLP=8).
// splits(row) = (tt>>9)+1, tt = row % TSEQ.
// ---------------------------------------------------------------------------
__global__ void __launch_bounds__(256) combine_kernel(float* __restrict__ Out)
{
    int idx = blockIdx.x * 256 + threadIdx.x;   // over BTROWS*16
    int r = idx >> 4;
    int tt = r & (TSEQ - 1);
    int ns = (tt >> 9) + 1;                     // floor(qt/4)+1, qt = tt>>7

    const __half* base = g_Oph + (size_t)idx * 4;
    float la = 0.f, lb = 0.f;
    float a0 = 0.f, a1 = 0.f, a2 = 0.f, a3 = 0.f;
    float b0 = 0.f, b1 = 0.f, b2 = 0.f, b3 = 0.f;

#pragma unroll
    for (int s = 0; s < 8; s += 2) {
        if (s < ns) {
            la += g_L[(size_t)s * BTROWS + r];
            uint2 u = *(const uint2*)(base + (size_t)s * BTROWS * HS);
            float2 f0 = __half22float2(*(__half2*)&u.x);
            float2 f1 = __half22float2(*(__half2*)&u.y);
            a0 += f0.x; a1 += f0.y; a2 += f1.x; a3 += f1.y;
        }
        if (s + 1 < ns) {
            lb += g_L[(size_t)(s + 1) * BTROWS + r];
            uint2 u = *(const uint2*)(base + (size_t)(s + 1) * BTROWS * HS);
            float2 f0 = __half22float2(*(__half2*)&u.x);
            float2 f1 = __half22float2(*(__half2*)&u.y);
            b0 += f0.x; b1 += f0.y; b2 += f1.x; b3 += f1.y;
        }
    }

    float rinv = 1.f / (la + lb);
    float4 v;
    v.x = (a0 + b0) * rinv;
    v.y = (a1 + b1) * rinv;
    v.z = (a2 + b2) * rinv;
    v.w = (a3 + b3) * rinv;
    ((float4*)Out)[idx] = v;
}

// ---------------------------------------------------------------------------
extern "C" void kernel_launch(void* const* d_in, const int* in_sizes, int n_in,
                              void* d_out, int out_size)
{
    const float* x  = (const float*)d_in[0];
    const float* Wq = (const float*)d_in[1];
    const float* Wk = (const float*)d_in[2];
    const float* Wv = (const float*)d_in[3];
    float* Out = (float*)d_out;

    static int configured = 0;
    if (!configured) {
        cudaFuncSetAttribute(qkv_gemm,
                             cudaFuncAttributeMaxDynamicSharedMemorySize, QKV_SMEM);
        cudaFuncSetAttribute(attn_kernel,
                             cudaFuncAttributeMaxDynamicSharedMemorySize, ATT_SMEM);
        configured = 1;
    }

    wt_kernel<<<192, 256>>>(Wq, Wk, Wv);
    qkv_gemm<<<BTROWS / 128, 256, QKV_SMEM>>>(x);
    attn_kernel<<<dim3(NCHUNK, NB), 256, ATT_SMEM>>>();
    combine_kernel<<<BTROWS * 16 / 256, 256>>>(Out);
}

// round 12
// speedup vs baseline: 1.1225x; 1.0300x over previous
#include <cuda_runtime.h>
#include <cuda_fp16.h>
#include <math.h>
#include <stdint.h>

#define NB    4
#define TSEQ  4096
#define EMB   1024
#define HS    64
#define BTROWS (NB * TSEQ)   // 16384
#define NSPLIT 8
#define NCHUNK 144           // sum over qt=0..31 of floor(qt/4)+1

// Device-global scratch (no allocation)
__device__ __half g_Qh[BTROWS * HS];              // pre-scaled by log2(e)/32
__device__ __half g_Kh[BTROWS * HS];
__device__ __half g_Vh[BTROWS * HS];
__device__ __half g_Wt[192 * EMB];                // [n][k]
__device__ __half g_Oph[NSPLIT * BTROWS * HS];    // partial O per split (fp16)
__device__ float  g_L  [NSPLIT * BTROWS];         // partial l per split

// ---------------------------------------------------------------------------
// helpers
// ---------------------------------------------------------------------------
__device__ __forceinline__ uint32_t smem_u32(const void* p) {
    uint32_t a;
    asm("{ .reg .u64 t; cvta.to.shared.u64 t, %1; cvt.u32.u64 %0, t; }" : "=r"(a) : "l"(p));
    return a;
}
__device__ __forceinline__ void ldsm_x4(uint32_t a, uint32_t* r) {
    asm volatile("ldmatrix.sync.aligned.m8n8.x4.shared.b16 {%0,%1,%2,%3}, [%4];"
                 : "=r"(r[0]), "=r"(r[1]), "=r"(r[2]), "=r"(r[3]) : "r"(a));
}
__device__ __forceinline__ void ldsm_x4t(uint32_t a, uint32_t* r) {
    asm volatile("ldmatrix.sync.aligned.m8n8.x4.trans.shared.b16 {%0,%1,%2,%3}, [%4];"
                 : "=r"(r[0]), "=r"(r[1]), "=r"(r[2]), "=r"(r[3]) : "r"(a));
}
// fp32-accumulate (PV, QKV)
#define MMA16816(C, A0, A1, A2, A3, B0, B1)                                    \
    asm volatile("mma.sync.aligned.m16n8k16.row.col.f32.f16.f16.f32 "          \
                 "{%0,%1,%2,%3}, {%4,%5,%6,%7}, {%8,%9}, {%0,%1,%2,%3};"       \
                 : "+f"((C)[0]), "+f"((C)[1]), "+f"((C)[2]), "+f"((C)[3])      \
                 : "r"(A0), "r"(A1), "r"(A2), "r"(A3), "r"(B0), "r"(B1))
// fp16-accumulate (S only): D = {row g | row g+8} packed half2
#define MMA16816H(C0, C1, A0, A1, A2, A3, B0, B1)                              \
    asm volatile("mma.sync.aligned.m16n8k16.row.col.f16.f16.f16.f16 "          \
                 "{%0,%1}, {%2,%3,%4,%5}, {%6,%7}, {%0,%1};"                   \
                 : "+r"(C0), "+r"(C1)                                          \
                 : "r"(A0), "r"(A1), "r"(A2), "r"(A3), "r"(B0), "r"(B1))
__device__ __forceinline__ uint32_t ex2_h2(uint32_t x) {
    uint32_t r;
    asm("ex2.approx.f16x2 %0, %1;" : "=r"(r) : "r"(x));
    return r;
}
__device__ __forceinline__ void cp16(uint32_t dst, const void* src) {
    asm volatile("cp.async.cg.shared.global [%0], [%1], 16;" :: "r"(dst), "l"(src));
}
#define CP_COMMIT() asm volatile("cp.async.commit_group;" ::: "memory")
#define CP_WAIT0()  asm volatile("cp.async.wait_group 0;" ::: "memory")

// half -60.0: ex2(-60) underflows to exactly 0 in fp16
#define HNEG60 0xD380u

// ---------------------------------------------------------------------------
// Kernel 0: coalesced transpose+convert W -> g_Wt[n][k] fp16.
// ---------------------------------------------------------------------------
__global__ void __launch_bounds__(256) wt_kernel(
    const float* __restrict__ Wq, const float* __restrict__ Wk,
    const float* __restrict__ Wv)
{
    __shared__ float ts[32][33];
    const int n0 = (blockIdx.x % 6) * 32;
    const int k0 = (blockIdx.x / 6) * 32;
    const int tx = threadIdx.x & 31;
    const int ty = threadIdx.x >> 5;
    const float* W = (n0 < 64) ? Wq : (n0 < 128) ? Wk : Wv;
    const int nc = n0 & 63;
#pragma unroll
    for (int i = 0; i < 4; ++i) {
        int k = k0 + ty + i * 8;
        ts[ty + i * 8][tx] = W[(size_t)k * 64 + nc + tx];
    }
    __syncthreads();
#pragma unroll
    for (int i = 0; i < 4; ++i) {
        int n = n0 + ty + i * 8;
        g_Wt[(size_t)n * EMB + k0 + tx] = __float2half_rn(ts[tx][ty + i * 8]);
    }
}

// ---------------------------------------------------------------------------
// Kernel 1: QKV GEMM, 128 rows x 192 cols per CTA (grid 128 = one wave).
// ---------------------------------------------------------------------------
#define QKV_SMEM 157696
#define XG_OFF   0
#define XS_OFF   65536
#define WS_OFF   102400

__global__ void __launch_bounds__(256) qkv_gemm(const float* __restrict__ x)
{
    extern __shared__ char qsm[];

    const int tid  = threadIdx.x;
    const int lane = tid & 31;
    const int wid  = tid >> 5;
    const int wm   = wid & 3;
    const int wn   = wid >> 2;
    const int g    = lane >> 2;
    const int t    = lane & 3;
    const int t16  = lane & 15;
    const int row0 = blockIdx.x * 128;

    const uint32_t sb = smem_u32(qsm);
    const uint32_t dXG[2] = { sb + XG_OFF, sb + XG_OFF + 32768 };
    const uint32_t dXS[2] = { sb + XS_OFF, sb + XS_OFF + 18432 };
    const uint32_t dWS[2] = { sb + WS_OFF, sb + WS_OFF + 27648 };

    const uint32_t xOff = ((wm * 32 + t16) * 72 + (lane >> 4) * 8) * 2;
    const uint32_t wOff = ((wn * 96 + t16) * 72 + (lane >> 4) * 8) * 2;

    const int xr_r = tid >> 4, xr_c4 = tid & 15;

    float c[2][12][4];
#pragma unroll
    for (int mh = 0; mh < 2; ++mh)
#pragma unroll
        for (int nt = 0; nt < 12; ++nt)
#pragma unroll
            for (int e = 0; e < 4; ++e) c[mh][nt][e] = 0.f;

#pragma unroll
    for (int u = 0; u < 8; ++u) {
        int r = xr_r + 16 * u;
        cp16(dXG[0] + r * 256 + xr_c4 * 16,
             x + (size_t)(row0 + r) * EMB + xr_c4 * 4);
    }
#pragma unroll
    for (int i = tid; i < 1536; i += 256) {
        int r = i >> 3, c8 = i & 7;
        cp16(dWS[0] + (r * 72 + c8 * 8) * 2, g_Wt + (size_t)r * EMB + c8 * 8);
    }
    CP_COMMIT();

    int buf = 0;
    for (int it = 0; it < 16; ++it, buf ^= 1) {
        const int cc = it * 64;
        CP_WAIT0();
        __syncthreads();

#pragma unroll
        for (int u = 0; u < 8; ++u) {
            int r = xr_r + 16 * u;
            float4 f = *(const float4*)(qsm + XG_OFF + (buf ? 32768 : 0)
                                            + r * 256 + xr_c4 * 16);
            __half2 h01 = __floats2half2_rn(f.x, f.y);
            __half2 h23 = __floats2half2_rn(f.z, f.w);
            uint2 uh;
            uh.x = *(uint32_t*)&h01; uh.y = *(uint32_t*)&h23;
            *(uint2*)(qsm + XS_OFF + (buf ? 18432 : 0) + r * 144 + xr_c4 * 8) = uh;
        }
        __syncthreads();

        if (it + 1 < 16) {
#pragma unroll
            for (int u = 0; u < 8; ++u) {
                int r = xr_r + 16 * u;
                cp16(dXG[buf ^ 1] + r * 256 + xr_c4 * 16,
                     x + (size_t)(row0 + r) * EMB + cc + 64 + xr_c4 * 4);
            }
#pragma unroll
            for (int i = tid; i < 1536; i += 256) {
                int r = i >> 3, c8 = i & 7;
                cp16(dWS[buf ^ 1] + (r * 72 + c8 * 8) * 2,
                     g_Wt + (size_t)r * EMB + cc + 64 + c8 * 8);
            }
            CP_COMMIT();
        }

        const uint32_t aX = dXS[buf] + xOff;
        const uint32_t aW = dWS[buf] + wOff;
#pragma unroll
        for (int ks = 0; ks < 4; ++ks) {
            uint32_t ah[2][4];
            ldsm_x4(aX + ks * 32, ah[0]);
            ldsm_x4(aX + 16 * 144 + ks * 32, ah[1]);
#pragma unroll
            for (int np = 0; np < 6; ++np) {
                uint32_t bw[4];
                ldsm_x4(aW + (np * 16 * 72 + ks * 16) * 2, bw);
#pragma unroll
                for (int mh = 0; mh < 2; ++mh) {
                    MMA16816(c[mh][2 * np + 0], ah[mh][0], ah[mh][1], ah[mh][2], ah[mh][3],
                             bw[0], bw[2]);
                    MMA16816(c[mh][2 * np + 1], ah[mh][0], ah[mh][1], ah[mh][2], ah[mh][3],
                             bw[1], bw[3]);
                }
            }
        }
    }

#pragma unroll
    for (int mh = 0; mh < 2; ++mh) {
        const int r0 = row0 + wm * 32 + mh * 16 + g;
#pragma unroll
        for (int nt = 0; nt < 12; ++nt) {
            int n0 = wn * 96 + nt * 8 + 2 * t;
            int mat = n0 >> 6, col = n0 & 63;
            __half* base = (mat == 0) ? g_Qh : (mat == 1) ? g_Kh : g_Vh;
            float sc = (mat == 0) ? 0.045084220f : 1.0f;
            __half2 v0 = __floats2half2_rn(c[mh][nt][0] * sc, c[mh][nt][1] * sc);
            __half2 v1 = __floats2half2_rn(c[mh][nt][2] * sc, c[mh][nt][3] * sc);
            *(__half2*)(base + (size_t)r0 * HS + col)       = v0;
            *(__half2*)(base + (size_t)(r0 + 8) * HS + col) = v1;
        }
    }
}

// ---------------------------------------------------------------------------
// Kernel 2: causal attention (chunks of <=8 key-tiles, R9 schedule).
// 128-query CTAs, 8 warps; warp = 16 rows x all 64 keys; register-resident P.
// S phase split into two key-halves to cap register pressure (no spills at
// the 128-reg/thread occupancy-2 limit). S fp16-acc; PV fp32-acc.
// ---------------------------------------------------------------------------
#define ATT_SMEM 55296

__global__ void __launch_bounds__(256, 2) attn_kernel()
{
    extern __shared__ char asm_[];
    __half* Qs = (__half*)asm_;                       // [128][72]
    const uint32_t sb = smem_u32(asm_);
    const uint32_t dK[2] = { sb + 18432, sb + 27648 };
    const uint32_t dV[2] = { sb + 36864, sb + 46080 };

    const int tid  = threadIdx.x;
    const int lane = tid & 31;
    const int wm   = tid >> 5;       // 0..7
    const int g    = lane >> 2;
    const int t    = lane & 3;
    const int t16  = lane & 15;
    const int b    = blockIdx.y;

    // ---- chunk -> (qt, ci, [k0,k1)); splits(qt) = floor(qt/4)+1
    int cid = (NCHUNK - 1) - (int)blockIdx.x;   // heavy chunks first
    int gg = 7;
    while (cid < 2 * gg * (gg + 1)) --gg;
    int off = cid - 2 * gg * (gg + 1);
    int qt  = 4 * gg + off / (gg + 1);
    int ci  = off % (gg + 1);
    int nt_ = 2 * qt + 2;
    int k0 = ci * nt_ / (gg + 1);
    int k1 = (ci + 1) * nt_ / (gg + 1);
    const int qbase = qt * 128;

    const __half* Kg = g_Kh + (size_t)b * TSEQ * HS;
    const __half* Vg = g_Vh + (size_t)b * TSEQ * HS;

    // ---- stage Q [128 x 64]
    {
        const uint4* Qgp = (const uint4*)(g_Qh + ((size_t)b * TSEQ + qbase) * HS);
#pragma unroll
        for (int i = tid; i < 1024; i += 256) {
            int r = i >> 3, c8 = i & 7;
            *(uint4*)(Qs + r * 72 + c8 * 8) = Qgp[i];
        }
    }
    // ---- cp.async first K/V tile into buf 0
    {
        const __half* ks = Kg + (size_t)k0 * 64 * HS;
        const __half* vs = Vg + (size_t)k0 * 64 * HS;
#pragma unroll
        for (int i = tid; i < 512; i += 256) {
            int r = i >> 3, c8 = i & 7;
            cp16(dK[0] + (r * 72 + c8 * 8) * 2, ks + i * 8);
            cp16(dV[0] + (r * 72 + c8 * 8) * 2, vs + i * 8);
        }
        CP_COMMIT();
    }
    CP_WAIT0();
    __syncthreads();

    // ---- Q fragments (tile-invariant, registers)
    uint32_t qf[4][4];
    {
        const uint32_t aQ = sb + ((wm * 16 + t16) * 72 + (lane >> 4) * 8) * 2;
#pragma unroll
        for (int ks = 0; ks < 4; ++ks) ldsm_x4(aQ + ks * 32, qf[ks]);
    }

    const uint32_t offK = (((lane & 7) + ((lane & 16) >> 1)) * 72 + ((lane >> 3) & 1) * 8) * 2;
    const uint32_t offV = ((lane & 15) * 72 + ((lane & 16) >> 1)) * 2;

    float o[8][4];
#pragma unroll
    for (int nt = 0; nt < 8; ++nt)
#pragma unroll
        for (int e = 0; e < 4; ++e) o[nt][e] = 0.f;
    float lsum0 = 0.f, lsum1 = 0.f;

    const int row0 = qbase + wm * 16 + g;

    int buf = 0;
    for (int kt = k0; kt < k1; ++kt, buf ^= 1) {
        if (kt + 1 < k1) {
            const __half* ks = Kg + (size_t)(kt + 1) * 64 * HS;
            const __half* vs = Vg + (size_t)(kt + 1) * 64 * HS;
#pragma unroll
            for (int i = tid; i < 512; i += 256) {
                int r = i >> 3, c8 = i & 7;
                cp16(dK[buf ^ 1] + (r * 72 + c8 * 8) * 2, ks + i * 8);
                cp16(dV[buf ^ 1] + (r * 72 + c8 * 8) * 2, vs + i * 8);
            }
            CP_COMMIT();
        }

        // ---- S = Q . K^T in two key-halves (keeps transient regs low)
        const bool diag = (kt >= 2 * qt);
        const uint32_t sKb = dK[buf] + offK;
        uint32_t pk[8][2];
        __half2 lacc0 = __float2half2_rn(0.f), lacc1 = __float2half2_rn(0.f);
#pragma unroll
        for (int h = 0; h < 2; ++h) {
            uint32_t ch[4][2];
#pragma unroll
            for (int n4 = 0; n4 < 4; ++n4) { ch[n4][0] = 0u; ch[n4][1] = 0u; }
#pragma unroll
            for (int ks = 0; ks < 4; ++ks) {
                uint32_t kr[2][4];
                ldsm_x4(sKb + ((2 * h)     * 16 * 72 + ks * 16) * 2, kr[0]);
                ldsm_x4(sKb + ((2 * h + 1) * 16 * 72 + ks * 16) * 2, kr[1]);
#pragma unroll
                for (int n4 = 0; n4 < 4; ++n4)
                    MMA16816H(ch[n4][0], ch[n4][1],
                              qf[ks][0], qf[ks][1], qf[ks][2], qf[ks][3],
                              kr[n4 >> 1][(n4 & 1) * 2], kr[n4 >> 1][(n4 & 1) * 2 + 1]);
            }
            // softmax (fixed max) for this half: mask by byte-splice, ex2
#pragma unroll
            for (int n4 = 0; n4 < 4; ++n4) {
                const int nt = 4 * h + n4;
                uint32_t v0 = ch[n4][0];   // row g,   cols 2t,2t+1 (packed)
                uint32_t v1 = ch[n4][1];   // row g+8
                if (diag) {
                    const int col0 = kt * 64 + nt * 8 + 2 * t;
                    if (col0     > row0)     v0 = (v0 & 0xFFFF0000u) | HNEG60;
                    if (col0 + 1 > row0)     v0 = (v0 & 0x0000FFFFu) | (HNEG60 << 16);
                    if (col0     > row0 + 8) v1 = (v1 & 0xFFFF0000u) | HNEG60;
                    if (col0 + 1 > row0 + 8) v1 = (v1 & 0x0000FFFFu) | (HNEG60 << 16);
                }
                uint32_t p01 = ex2_h2(v0);
                uint32_t p23 = ex2_h2(v1);
                pk[nt][0] = p01;
                pk[nt][1] = p23;
                lacc0 = __hadd2(lacc0, *(__half2*)&p01);
                lacc1 = __hadd2(lacc1, *(__half2*)&p23);
            }
        }
        lsum0 += __low2float(lacc0) + __high2float(lacc0);
        lsum1 += __low2float(lacc1) + __high2float(lacc1);

        // ---- O += P . V  (fp32 accumulate)
        const uint32_t sVb = dV[buf] + offV;
#pragma unroll
        for (int ks = 0; ks < 4; ++ks) {
            uint32_t vr[4][4];
#pragma unroll
            for (int np = 0; np < 4; ++np)
                ldsm_x4t(sVb + (ks * 16 * 72 + np * 16) * 2, vr[np]);
#pragma unroll
            for (int nt = 0; nt < 8; ++nt)
                MMA16816(o[nt], pk[2 * ks][0], pk[2 * ks][1],
                         pk[2 * ks + 1][0], pk[2 * ks + 1][1],
                         vr[nt >> 1][(nt & 1) * 2], vr[nt >> 1][(nt & 1) * 2 + 1]);
        }

        if (kt + 1 < k1) {
            CP_WAIT0();
            __syncthreads();
        }
    }

    // ---- epilogue
    lsum0 += __shfl_xor_sync(0xffffffffu, lsum0, 1);
    lsum0 += __shfl_xor_sync(0xffffffffu, lsum0, 2);
    lsum1 += __shfl_xor_sync(0xffffffffu, lsum1, 1);
    lsum1 += __shfl_xor_sync(0xffffffffu, lsum1, 2);

    const size_t pbase = (size_t)(ci * NB + b) * TSEQ + qbase + wm * 16 + g;
    if (t == 0) {
        g_L[pbase]     = lsum0;
        g_L[pbase + 8] = lsum1;
    }

    __half* og0 = g_Oph + pbase * HS + 2 * t;
    __half* og1 = og0 + 8 * HS;
#pragma unroll
    for (int nt = 0; nt < 8; ++nt) {
        *(__half2*)(og0 + nt * 8) = __floats2half2_rn(o[nt][0], o[nt][1]);
        *(__half2*)(og1 + nt * 8) = __floats2half2_rn(o[nt][2], o[nt][3]);
    }
}

// ---------------------------------------------------------------------------
// Kernel 3: combine <=8 splits, fully unrolled with predication (MLP=8).
// ---------------------------------------------------------------------------
__global__ void __launch_bounds__(256) combine_kernel(float* __restrict__ Out)
{
    int idx = blockIdx.x * 256 + threadIdx.x;   // over BTROWS*16
    int r = idx >> 4;
    int tt = r & (TSEQ - 1);
    int ns = (tt >> 9) + 1;                     // floor(qt/4)+1, qt = tt>>7

    const __half* base = g_Oph + (size_t)idx * 4;
    float la = 0.f, lb = 0.f;
    float a0 = 0.f, a1 = 0.f, a2 = 0.f, a3 = 0.f;
    float b0 = 0.f, b1 = 0.f, b2 = 0.f, b3 = 0.f;

#pragma unroll
    for (int s = 0; s < 8; s += 2) {
        if (s < ns) {
            la += g_L[(size_t)s * BTROWS + r];
            uint2 u = *(const uint2*)(base + (size_t)s * BTROWS * HS);
            float2 f0 = __half22float2(*(__half2*)&u.x);
            float2 f1 = __half22float2(*(__half2*)&u.y);
            a0 += f0.x; a1 += f0.y; a2 += f1.x; a3 += f1.y;
        }
        if (s + 1 < ns) {
            lb += g_L[(size_t)(s + 1) * BTROWS + r];
            uint2 u = *(const uint2*)(base + (size_t)(s + 1) * BTROWS * HS);
            float2 f0 = __half22float2(*(__half2*)&u.x);
            float2 f1 = __half22float2(*(__half2*)&u.y);
            b0 += f0.x; b1 += f0.y; b2 += f1.x; b3 += f1.y;
        }
    }

    float rinv = 1.f / (la + lb);
    float4 v;
    v.x = (a0 + b0) * rinv;
    v.y = (a1 + b1) * rinv;
    v.z = (a2 + b2) * rinv;
    v.w = (a3 + b3) * rinv;
    ((float4*)Out)[idx] = v;
}

// ---------------------------------------------------------------------------
extern "C" void kernel_launch(void* const* d_in, const int* in_sizes, int n_in,
                              void* d_out, int out_size)
{
    const float* x  = (const float*)d_in[0];
    const float* Wq = (const float*)d_in[1];
    const float* Wk = (const float*)d_in[2];
    const float* Wv = (const float*)d_in[3];
    float* Out = (float*)d_out;

    static int configured = 0;
    if (!configured) {
        cudaFuncSetAttribute(qkv_gemm,
                             cudaFuncAttributeMaxDynamicSharedMemorySize, QKV_SMEM);
        cudaFuncSetAttribute(attn_kernel,
                             cudaFuncAttributeMaxDynamicSharedMemorySize, ATT_SMEM);
        configured = 1;
    }

    wt_kernel<<<192, 256>>>(Wq, Wk, Wv);
    qkv_gemm<<<BTROWS / 128, 256, QKV_SMEM>>>(x);
    attn_kernel<<<dim3(NCHUNK, NB), 256, ATT_SMEM>>>();
    combine_kernel<<<BTROWS * 16 / 256, 256>>>(Out);
}